// round 10
// baseline (speedup 1.0000x reference)
#include <cuda_runtime.h>
#include <cuda_bf16.h>

// EarthAttention2D v8: full HMMA, register-resident attention, pipelined
// wfrag loads, frag-pair (u64) smem image layout for all operands.

typedef unsigned long long u64;
typedef unsigned int u32;
typedef unsigned short u16;

#define NTOK 72
#define DIMX 192
#define NH 6
#define TOWC 31
#define NWC 30
#define BLK 384
#define NSQ 5184
#define TBLROWS 828

// u32-unit shared offsets
#define U_QH 0        // q / attn-out hi: [72][100] frag-pair layout
#define U_QL 7200
#define U_KH 14400    // k hi: [72][100] frag-pair layout
#define U_KL 21600
#define U_VTH 28800   // v^T hi: [192][40] frag-pair layout
#define U_VTL 36480
#define U_PIDX 44160  // posv*6 u16 [5184] (2592 u32)
#define U_TB 46752    // bias slice bf16 [828*6] (2484 u32)
#define SMEM_BYTES (49236 * 4)   // 196944

// Pre-packed W^T A-fragments (hi/lo), register-exact m16n8k16 layout.
// u32 index = ((ct*12 + k)*2 + prec)*128 + lane*4 + r
__device__ u32 g_wfrag[147456];

// ---------------- helpers ----------------
__device__ __forceinline__ void mma16816(float* d, const u32* a, const u32* b) {
    asm("mma.sync.aligned.m16n8k16.row.col.f32.bf16.bf16.f32 "
        "{%0,%1,%2,%3}, {%4,%5,%6,%7}, {%8,%9}, {%0,%1,%2,%3};"
        : "+f"(d[0]), "+f"(d[1]), "+f"(d[2]), "+f"(d[3])
        : "r"(a[0]), "r"(a[1]), "r"(a[2]), "r"(a[3]), "r"(b[0]), "r"(b[1]));
}
__device__ __forceinline__ void mma16808(float* d, const u32* a, u32 b) {
    asm("mma.sync.aligned.m16n8k8.row.col.f32.bf16.bf16.f32 "
        "{%0,%1,%2,%3}, {%4,%5}, {%6}, {%0,%1,%2,%3};"
        : "+f"(d[0]), "+f"(d[1]), "+f"(d[2]), "+f"(d[3])
        : "r"(a[0]), "r"(a[1]), "r"(b));
}
__device__ __forceinline__ u32 packbf(float x0, float x1, u32& lo) {
    __nv_bfloat16 h0 = __float2bfloat16(x0), h1 = __float2bfloat16(x1);
    __nv_bfloat16 l0 = __float2bfloat16(x0 - __bfloat162float(h0));
    __nv_bfloat16 l1 = __float2bfloat16(x1 - __bfloat162float(h1));
    lo = (u32)__bfloat16_as_ushort(l0) | ((u32)__bfloat16_as_ushort(l1) << 16);
    return (u32)__bfloat16_as_ushort(h0) | ((u32)__bfloat16_as_ushort(h1) << 16);
}
__device__ __forceinline__ void bf_split(float v, u32& h, u32& l) {
    __nv_bfloat16 hb = __float2bfloat16(v);
    h = (u32)__bfloat16_as_ushort(hb);
    l = (u32)__bfloat16_as_ushort(__float2bfloat16(v - __bfloat162float(hb)));
}
__device__ __forceinline__ float tbf(u16 b) {
    return __bfloat162float(__ushort_as_bfloat16(b));
}
// frag-pair remap: old pair-col c -> new pair-col (adjacent k-halves)
__device__ __forceinline__ int remap96(int c) {
    return (c & ~7) + (c & 3) * 2 + ((c >> 2) & 1);
}

// ---------------- pre-kernel: pack W^T fragments ----------------
__global__ void build_wfrags(const float* __restrict__ wqkv,
                             const float* __restrict__ wout) {
    int idx = blockIdx.x * 256 + threadIdx.x;
    int r    = idx & 3;
    int lane = (idx >> 2) & 31;
    int prec = (idx >> 7) & 1;
    int rest = idx >> 8;
    int k  = rest % 12;
    int ct = rest / 12;
    int g = lane >> 2, tid2 = lane & 3;
    int i  = g + (r & 1) * 8;
    int kk = tid2 * 2 + (r >> 1) * 8;
    int k_abs = k * 16 + kk;
    const float* W; int stride, n_abs;
    if (ct < 36) { W = wqkv; stride = 576; n_abs = ct * 16 + i; }
    else         { W = wout; stride = 192; n_abs = (ct - 36) * 16 + i; }
    float v0 = W[(size_t)k_abs * stride + n_abs];
    float v1 = W[(size_t)(k_abs + 1) * stride + n_abs];
    u32 lo;
    u32 hi = packbf(v0, v1, lo);
    g_wfrag[idx] = prec ? lo : hi;
}

// ---------------- projection pass: pipelined k-loop, u64 frag I/O ---------
// MODE 0: Q -> Qimg (deferred epi, *scale). 1: K -> Kimg. 2: V -> vTimg.
// MODE 3: out-proj -> global (B operand = attn-out in Qimg).
template<int MODE>
__device__ void proj_pass(int tid, const float* __restrict__ bias, float scale,
                          u32* smu, int ct_base, float* outg)
{
    const int w = tid >> 5, lane = tid & 31;
    const int cg = w & 3, rg = w >> 2;
    const int g = lane >> 2, tid2 = lane & 3;

    float acc[3][3][4];
#pragma unroll
    for (int c = 0; c < 3; c++)
#pragma unroll
        for (int rt = 0; rt < 3; rt++)
#pragma unroll
            for (int q = 0; q < 4; q++) acc[c][rt][q] = 0.0f;

    u32 ah[2][3][4], al[2][3][4];
    u64 bh[2][3], bl[2][3];

    // prologue: load k=0 into buffer 0
#pragma unroll
    for (int c = 0; c < 3; c++) {
        int ct = ct_base + cg * 3 + c;
        const u32* p = g_wfrag + (size_t)((ct * 12) * 2) * 128 + lane * 4;
        *(uint4*)ah[0][c] = *(const uint4*)p;
        *(uint4*)al[0][c] = *(const uint4*)(p + 128);
    }
#pragma unroll
    for (int rt = 0; rt < 3; rt++) {
        int row = (rg * 3 + rt) * 8 + g;
        int o = row * 100 + tid2 * 2;
        bh[0][rt] = *(const u64*)&smu[U_QH + o];
        bl[0][rt] = *(const u64*)&smu[U_QL + o];
    }

#pragma unroll
    for (int k = 0; k < 12; k++) {
        const int cur = k & 1, nxt = cur ^ 1;
        if (k < 11) {
            const int kn = k + 1;
#pragma unroll
            for (int c = 0; c < 3; c++) {
                int ct = ct_base + cg * 3 + c;
                const u32* p = g_wfrag + (size_t)((ct * 12 + kn) * 2) * 128 + lane * 4;
                *(uint4*)ah[nxt][c] = *(const uint4*)p;
                *(uint4*)al[nxt][c] = *(const uint4*)(p + 128);
            }
#pragma unroll
            for (int rt = 0; rt < 3; rt++) {
                int row = (rg * 3 + rt) * 8 + g;
                int o = row * 100 + kn * 8 + tid2 * 2;
                bh[nxt][rt] = *(const u64*)&smu[U_QH + o];
                bl[nxt][rt] = *(const u64*)&smu[U_QL + o];
            }
        }
#pragma unroll
        for (int c = 0; c < 3; c++)
#pragma unroll
            for (int rt = 0; rt < 3; rt++) {
                u32 bhv[2] = { (u32)bh[cur][rt], (u32)(bh[cur][rt] >> 32) };
                u32 blv[2] = { (u32)bl[cur][rt], (u32)(bl[cur][rt] >> 32) };
                mma16816(acc[c][rt], ah[cur][c], bhv);
                mma16816(acc[c][rt], al[cur][c], bhv);
                mma16816(acc[c][rt], ah[cur][c], blv);
            }
    }
    if (MODE == 0) __syncthreads();   // all X reads done before Qimg overwrite

    if (MODE <= 1) {
        const u32 uh = (MODE == 0) ? U_QH : U_KH;
        const u32 ul = uh + 7200;
#pragma unroll
        for (int c = 0; c < 3; c++) {
            int ctl = cg * 3 + c;
#pragma unroll
            for (int rt = 0; rt < 3; rt++) {
                int rbase = (rg * 3 + rt) * 8;
                u32 hb[4], lb[4];
#pragma unroll
                for (int q = 0; q < 4; q++) {
                    int feat = ctl * 16 + g + (q >> 1) * 8;
                    float v = (acc[c][rt][q] + __ldg(bias + feat)) * scale;
                    u32 h_, l_; bf_split(v, h_, l_);
                    u32 oh = __shfl_xor_sync(0xffffffffu, h_, 4);
                    u32 ol = __shfl_xor_sync(0xffffffffu, l_, 4);
                    hb[q] = h_ | (oh << 16);
                    lb[q] = l_ | (ol << 16);
                }
                if (!(g & 1)) {
                    int base = ctl * 8 + (g >> 1) * 2;
                    int rr0 = rbase + tid2 * 2, rr1 = rr0 + 1;
                    *(u64*)&smu[uh + rr0 * 100 + base] = (u64)hb[0] | ((u64)hb[2] << 32);
                    *(u64*)&smu[ul + rr0 * 100 + base] = (u64)lb[0] | ((u64)lb[2] << 32);
                    *(u64*)&smu[uh + rr1 * 100 + base] = (u64)hb[1] | ((u64)hb[3] << 32);
                    *(u64*)&smu[ul + rr1 * 100 + base] = (u64)lb[1] | ((u64)lb[3] << 32);
                }
            }
        }
    } else if (MODE == 2) {
#pragma unroll
        for (int c = 0; c < 3; c++) {
            int ctl = cg * 3 + c;
#pragma unroll
            for (int rt = 0; rt < 3; rt++) {
                int rbase = (rg * 3 + rt) * 8;
#pragma unroll
                for (int fp = 0; fp < 2; fp++) {
                    int F = ctl * 16 + g + fp * 8;
                    float b = __ldg(bias + F);
                    float v0 = acc[c][rt][fp * 2] + b;
                    float v1 = acc[c][rt][fp * 2 + 1] + b;
                    u32 lo; u32 hi = packbf(v0, v1, lo);
                    int tcol = (rbase >> 1) + tid2;
                    int nc = (tcol < 32) ? remap96(tcol) : tcol;
                    smu[U_VTH + F * 40 + nc] = hi;
                    smu[U_VTL + F * 40 + nc] = lo;
                }
            }
        }
    } else {
#pragma unroll
        for (int c = 0; c < 3; c++) {
            int ctl = cg * 3 + c;
#pragma unroll
            for (int rt = 0; rt < 3; rt++) {
                int rbase = (rg * 3 + rt) * 8;
#pragma unroll
                for (int q = 0; q < 4; q++) {
                    int feat = ctl * 16 + g + (q >> 1) * 8;
                    int rr = rbase + tid2 * 2 + (q & 1);
                    outg[rr * DIMX + feat] = acc[c][rt][q] + __ldg(bias + feat);
                }
            }
        }
    }
}

// ---------------- main kernel ----------------
__global__ __launch_bounds__(BLK, 1)
void earth_attn_kernel(
    const float* __restrict__ x,
    const float* __restrict__ mask,
    const float* __restrict__ bqkv,
    const float* __restrict__ bout,
    const float* __restrict__ tbl,
    float* __restrict__ out)
{
    extern __shared__ u32 smu[];
    const int c   = blockIdx.x;
    const int tid = threadIdx.x;
    const int wid = tid >> 5, lane = tid & 31;
    const int g = lane >> 2, tid2 = lane & 3;

    const int t_idx = c % TOWC;
    const int s_sh  = c / TOWC;
    const int m_idx = c % NWC;
    const float* maskg = mask + (size_t)m_idx * NSQ;
    const float* xsrc  = x + (size_t)c * (NTOK * DIMX);
    const float qscale = 0.1767766952966369f;
    u16* tb16 = (u16*)(smu + U_TB);
    u16* pidx = (u16*)(smu + U_PIDX);

    // ---- init: stage X into Qimg region (frag-pair layout), pidx, table ----
    for (int i = tid; i < NTOK * 48; i += BLK) {
        int r = i / 48, c4 = i - r * 48;
        float4 v = ((const float4*)xsrc)[i];
        u32 lo0, lo1;
        u32 hi0 = packbf(v.x, v.y, lo0);
        u32 hi1 = packbf(v.z, v.w, lo1);
        int o0 = r * 100 + remap96(c4 * 2);
        int o1 = r * 100 + remap96(c4 * 2 + 1);
        smu[U_QH + o0] = hi0; smu[U_QH + o1] = hi1;
        smu[U_QL + o0] = lo0; smu[U_QL + o1] = lo1;
    }
    for (int i = tid; i < NSQ; i += BLK) {
        int p = (i * 60 + s_sh) % NSQ;
        int n2 = p / NTOK, m2 = p - n2 * NTOK;
        int n12 = n2 / 12, m12 = m2 / 12;
        int posv = (n12 + 6 * m12) * 23 + (n2 - n12 * 12) - (m2 - m12 * 12) + 11;
        pidx[i] = (u16)(posv * NH);
    }
    for (int i = tid; i < TBLROWS * NH; i += BLK) {
        int r = i / NH, hh = i - r * NH;
        tb16[i] = __bfloat16_as_ushort(
            __float2bfloat16(__ldg(tbl + (r * TOWC + t_idx) * NH + hh)));
    }
    __syncthreads();

    // ---- projections (V, K first; Q last with deferred epi over X region)
    proj_pass<2>(tid, bqkv + 384, 1.0f,   smu, 24, nullptr);
    proj_pass<1>(tid, bqkv + 192, 1.0f,   smu, 12, nullptr);
    proj_pass<0>(tid, bqkv,       qscale, smu, 0,  nullptr);
    __syncthreads();

    // ---- attention: warp-independent (head, m-tile) tasks, no syncs ----
    for (int s4 = 0; s4 < 2; s4++) {
        int u = wid + s4 * 12;
        int h = u % 6;
        int stype = u / 6;
        int reps = (stype == 3) ? 2 : 1;
        for (int rep = 0; rep < reps; rep++) {
            int mt = (stype < 3) ? stype : (rep == 0 ? 4 : 3);
            int mb = (mt == 4) ? 56 : mt * 16;
            int r0 = mb + g, r1 = r0 + 8;

            // --- QK^T ---
            float acc[9][4];
#pragma unroll
            for (int nt = 0; nt < 9; nt++)
#pragma unroll
                for (int q = 0; q < 4; q++) acc[nt][q] = 0.0f;

            u32 ah[2][4], al[2][4];
#pragma unroll
            for (int ks = 0; ks < 2; ks++) {
                int o = (h * 2 + ks) * 8 + tid2 * 2;
                u64 q0h = *(const u64*)&smu[U_QH + r0 * 100 + o];
                u64 q1h = *(const u64*)&smu[U_QH + r1 * 100 + o];
                u64 q0l = *(const u64*)&smu[U_QL + r0 * 100 + o];
                u64 q1l = *(const u64*)&smu[U_QL + r1 * 100 + o];
                ah[ks][0] = (u32)q0h; ah[ks][2] = (u32)(q0h >> 32);
                ah[ks][1] = (u32)q1h; ah[ks][3] = (u32)(q1h >> 32);
                al[ks][0] = (u32)q0l; al[ks][2] = (u32)(q0l >> 32);
                al[ks][1] = (u32)q1l; al[ks][3] = (u32)(q1l >> 32);
            }
#pragma unroll
            for (int nt = 0; nt < 9; nt++) {
#pragma unroll
                for (int ks = 0; ks < 2; ks++) {
                    int kb = U_KH + (nt * 8 + g) * 100 + (h * 2 + ks) * 8 + tid2 * 2;
                    u64 th = *(const u64*)&smu[kb];
                    u64 tl = *(const u64*)&smu[kb + 7200];
                    u32 bh[2] = { (u32)th, (u32)(th >> 32) };
                    u32 bl[2] = { (u32)tl, (u32)(tl >> 32) };
                    mma16816(acc[nt], ah[ks], bh);
                    mma16816(acc[nt], al[ks], bh);
                    mma16816(acc[nt], ah[ks], bl);
                }
            }

            // --- bias (smem) + mask (direct from L2) ---
#pragma unroll
            for (int nt = 0; nt < 9; nt++) {
                int cc = nt * 8 + tid2 * 2;
                int e0 = r0 * 72 + cc, e1 = r1 * 72 + cc;
                float2 m0 = __ldg((const float2*)(maskg + e0));
                float2 m1 = __ldg((const float2*)(maskg + e1));
                acc[nt][0] += tbf(tb16[pidx[e0] + h])     + m0.x;
                acc[nt][1] += tbf(tb16[pidx[e0 + 1] + h]) + m0.y;
                acc[nt][2] += tbf(tb16[pidx[e1] + h])     + m1.x;
                acc[nt][3] += tbf(tb16[pidx[e1 + 1] + h]) + m1.y;
            }

            // --- softmax in registers ---
            float mx0 = -1e30f, mx1 = -1e30f;
#pragma unroll
            for (int nt = 0; nt < 9; nt++) {
                mx0 = fmaxf(mx0, fmaxf(acc[nt][0], acc[nt][1]));
                mx1 = fmaxf(mx1, fmaxf(acc[nt][2], acc[nt][3]));
            }
#pragma unroll
            for (int o = 1; o <= 2; o <<= 1) {
                mx0 = fmaxf(mx0, __shfl_xor_sync(0xffffffffu, mx0, o));
                mx1 = fmaxf(mx1, __shfl_xor_sync(0xffffffffu, mx1, o));
            }
            float s0 = 0.f, s1 = 0.f;
#pragma unroll
            for (int nt = 0; nt < 9; nt++) {
                acc[nt][0] = __expf(acc[nt][0] - mx0);
                acc[nt][1] = __expf(acc[nt][1] - mx0);
                acc[nt][2] = __expf(acc[nt][2] - mx1);
                acc[nt][3] = __expf(acc[nt][3] - mx1);
                s0 += acc[nt][0] + acc[nt][1];
                s1 += acc[nt][2] + acc[nt][3];
            }
#pragma unroll
            for (int o = 1; o <= 2; o <<= 1) {
                s0 += __shfl_xor_sync(0xffffffffu, s0, o);
                s1 += __shfl_xor_sync(0xffffffffu, s1, o);
            }
            float rv0 = 1.0f / s0, rv1 = 1.0f / s1;

            // --- pack P into A-fragments (register-to-register) ---
            u32 ph[4][4], pl[4][4], ph8[2], pl8[2];
#pragma unroll
            for (int j = 0; j < 4; j++) {
                ph[j][0] = packbf(acc[2*j][0] * rv0,   acc[2*j][1] * rv0,   pl[j][0]);
                ph[j][1] = packbf(acc[2*j][2] * rv1,   acc[2*j][3] * rv1,   pl[j][1]);
                ph[j][2] = packbf(acc[2*j+1][0] * rv0, acc[2*j+1][1] * rv0, pl[j][2]);
                ph[j][3] = packbf(acc[2*j+1][2] * rv1, acc[2*j+1][3] * rv1, pl[j][3]);
            }
            ph8[0] = packbf(acc[8][0] * rv0, acc[8][1] * rv0, pl8[0]);
            ph8[1] = packbf(acc[8][2] * rv1, acc[8][3] * rv1, pl8[1]);

            // --- AV: out = P @ v_h -> Qimg head-h cols (paired nt2 writes) ---
            bool w0 = (mt != 4);
#pragma unroll
            for (int np = 0; np < 2; np++) {
                float ova[4] = {0.f, 0.f, 0.f, 0.f};
                float ovb[4] = {0.f, 0.f, 0.f, 0.f};
#pragma unroll
                for (int half = 0; half < 2; half++) {
                    float* o2 = half ? ovb : ova;
                    int nt2 = np * 2 + half;
                    int vbase = U_VTH + (h * 32 + nt2 * 8 + g) * 40;
#pragma unroll
                    for (int j = 0; j < 4; j++) {
                        u64 th = *(const u64*)&smu[vbase + j * 8 + tid2 * 2];
                        u64 tl = *(const u64*)&smu[vbase + 7680 + j * 8 + tid2 * 2];
                        u32 bh[2] = { (u32)th, (u32)(th >> 32) };
                        u32 bl[2] = { (u32)tl, (u32)(tl >> 32) };
                        mma16816(o2, ph[j], bh);
                        mma16816(o2, pl[j], bh);
                        mma16816(o2, ph[j], bl);
                    }
                    {
                        u32 b8h = smu[vbase + 32 + tid2];
                        u32 b8l = smu[vbase + 7680 + 32 + tid2];
                        mma16808(o2, ph8, b8h);
                        mma16808(o2, pl8, b8h);
                        mma16808(o2, ph8, b8l);
                    }
                }
                int base = (h * 2 + np) * 8 + tid2 * 2;
                u32 lA, lB, lC, lD;
                u32 hA = packbf(ova[0], ova[1], lA);
                u32 hB = packbf(ovb[0], ovb[1], lB);
                u32 hC = packbf(ova[2], ova[3], lC);
                u32 hD = packbf(ovb[2], ovb[3], lD);
                if (w0) {
                    *(u64*)&smu[U_QH + r0 * 100 + base] = (u64)hA | ((u64)hB << 32);
                    *(u64*)&smu[U_QL + r0 * 100 + base] = (u64)lA | ((u64)lB << 32);
                }
                *(u64*)&smu[U_QH + r1 * 100 + base] = (u64)hC | ((u64)hD << 32);
                *(u64*)&smu[U_QL + r1 * 100 + base] = (u64)lC | ((u64)lD << 32);
            }
        }
    }
    __syncthreads();

    // ---- out projection (B = attn-out in Qimg) -> global ----
    proj_pass<3>(tid, bout, 1.0f, smu, 36, out + (size_t)c * (NTOK * DIMX));
}

extern "C" void kernel_launch(void* const* d_in, const int* in_sizes, int n_in,
                              void* d_out, int out_size)
{
    const float* x    = (const float*)d_in[0];
    const float* mask = (const float*)d_in[1];
    const float* wqkv = (const float*)d_in[2];
    const float* bqkv = (const float*)d_in[3];
    const float* wout = (const float*)d_in[4];
    const float* bout = (const float*)d_in[5];
    const float* tbl  = (const float*)d_in[6];
    float* out = (float*)d_out;

    int B_ = in_sizes[0] / (NTOK * DIMX);   // 1860

    build_wfrags<<<576, 256>>>(wqkv, wout);

    cudaFuncSetAttribute(earth_attn_kernel,
                         cudaFuncAttributeMaxDynamicSharedMemorySize, SMEM_BYTES);
    earth_attn_kernel<<<B_, BLK, SMEM_BYTES>>>(x, mask, bqkv, bout, tbl, out);
}

// round 13
// speedup vs baseline: 1.0908x; 1.0908x over previous
#include <cuda_runtime.h>
#include <cuda_bf16.h>

// EarthAttention2D v9: R7 layout (563us baseline) + precomputed pidx table
// (g_pidx, per-s_sh slice read from L2) + cvt.rn.bf16x2.f32 fast packing.

typedef unsigned long long u64;
typedef unsigned int u32;
typedef unsigned short u16;

#define NTOK 72
#define DIMX 192
#define NH 6
#define TOWC 31
#define NWC 30
#define BLK 384
#define NSQ 5184
#define TBLROWS 828
#define NSH 60

// u32-unit shared offsets
#define U_QH 0        // q / attn-out hi: [72][100]
#define U_QL 7200
#define U_KH 14400    // k hi: [72][100]
#define U_KL 21600
#define U_VTH 28800   // v^T hi: [192][40]
#define U_VTL 36480
#define U_TB 44160    // bias slice bf16 [828*6] (2484 u32)
#define SMEM_BYTES (46644 * 4)   // 186576

// Pre-packed W^T A-fragments (hi/lo), register-exact m16n8k16 layout.
// u32 index = ((ct*12 + k)*2 + prec)*128 + lane*4 + r
__device__ u32 g_wfrag[147456];
// Precomputed relative-position index: g_pidx[s_sh][e] = posv(e,s_sh)*NH
__device__ u16 g_pidx[NSH * NSQ];

// ---------------- helpers ----------------
__device__ __forceinline__ void mma16816(float* d, const u32* a, const u32* b) {
    asm("mma.sync.aligned.m16n8k16.row.col.f32.bf16.bf16.f32 "
        "{%0,%1,%2,%3}, {%4,%5,%6,%7}, {%8,%9}, {%0,%1,%2,%3};"
        : "+f"(d[0]), "+f"(d[1]), "+f"(d[2]), "+f"(d[3])
        : "r"(a[0]), "r"(a[1]), "r"(a[2]), "r"(a[3]), "r"(b[0]), "r"(b[1]));
}
__device__ __forceinline__ void mma16808(float* d, const u32* a, u32 b) {
    asm("mma.sync.aligned.m16n8k8.row.col.f32.bf16.bf16.f32 "
        "{%0,%1,%2,%3}, {%4,%5}, {%6}, {%0,%1,%2,%3};"
        : "+f"(d[0]), "+f"(d[1]), "+f"(d[2]), "+f"(d[3])
        : "r"(a[0]), "r"(a[1]), "r"(b));
}
// pack two f32 to bf16x2 in one cvt (low = x0, high = x1)
__device__ __forceinline__ u32 cvt2(float x0, float x1) {
    u32 d;
    asm("cvt.rn.bf16x2.f32 %0, %1, %2;" : "=r"(d) : "f"(x1), "f"(x0));
    return d;
}
__device__ __forceinline__ u32 packbf(float x0, float x1, u32& lo) {
    u32 hi = cvt2(x0, x1);
    float h0 = __uint_as_float(hi << 16);
    float h1 = __uint_as_float(hi & 0xffff0000u);
    lo = cvt2(x0 - h0, x1 - h1);
    return hi;
}
__device__ __forceinline__ void bf_split(float v, u32& h, u32& l) {
    u32 p = cvt2(v, 0.0f);
    h = p & 0xffffu;
    float hf = __uint_as_float(p << 16);
    u32 p2 = cvt2(v - hf, 0.0f);
    l = p2 & 0xffffu;
}
__device__ __forceinline__ float tbf(u16 b) {
    return __bfloat162float(__ushort_as_bfloat16(b));
}

// ---------------- pre-kernels ----------------
__global__ void build_wfrags(const float* __restrict__ wqkv,
                             const float* __restrict__ wout) {
    int idx = blockIdx.x * 256 + threadIdx.x;
    int r    = idx & 3;
    int lane = (idx >> 2) & 31;
    int prec = (idx >> 7) & 1;
    int rest = idx >> 8;
    int k  = rest % 12;
    int ct = rest / 12;
    int g = lane >> 2, tid2 = lane & 3;
    int i  = g + (r & 1) * 8;
    int kk = tid2 * 2 + (r >> 1) * 8;
    int k_abs = k * 16 + kk;
    const float* W; int stride, n_abs;
    if (ct < 36) { W = wqkv; stride = 576; n_abs = ct * 16 + i; }
    else         { W = wout; stride = 192; n_abs = (ct - 36) * 16 + i; }
    float v0 = W[(size_t)k_abs * stride + n_abs];
    float v1 = W[(size_t)(k_abs + 1) * stride + n_abs];
    u32 lo;
    u32 hi = packbf(v0, v1, lo);
    g_wfrag[idx] = prec ? lo : hi;
}

__global__ void build_pidx() {
    int i = blockIdx.x * 256 + threadIdx.x;
    if (i >= NSH * NSQ) return;
    int s_sh = i / NSQ, e = i - s_sh * NSQ;
    int p = (e * 60 + s_sh) % NSQ;
    int n2 = p / NTOK, m2 = p - n2 * NTOK;
    int n12 = n2 / 12, m12 = m2 / 12;
    int posv = (n12 + 6 * m12) * 23 + (n2 - n12 * 12) - (m2 - m12 * 12) + 11;
    g_pidx[i] = (u16)(posv * NH);
}

// ---------------- projection pass: pipelined k-loop (R7-validated) --------
// MODE 0: Q -> Qimg (deferred epi, *scale). 1: K -> Kimg. 2: V -> vTimg.
// MODE 3: out-proj -> global (B operand = attn-out in Qimg).
template<int MODE>
__device__ void proj_pass(int tid, const float* __restrict__ bias, float scale,
                          u32* smu, int ct_base, float* outg)
{
    const int w = tid >> 5, lane = tid & 31;
    const int cg = w & 3, rg = w >> 2;
    const int g = lane >> 2, tid2 = lane & 3;
    const u32* Ah32 = smu + U_QH;
    const u32* Al32 = smu + U_QL;

    float acc[3][3][4];
#pragma unroll
    for (int c = 0; c < 3; c++)
#pragma unroll
        for (int rt = 0; rt < 3; rt++)
#pragma unroll
            for (int q = 0; q < 4; q++) acc[c][rt][q] = 0.0f;

    u32 ah[2][3][4], al[2][3][4], bh[2][3][2], bl[2][3][2];

    // prologue: load k=0 into buffer 0
#pragma unroll
    for (int c = 0; c < 3; c++) {
        int ct = ct_base + cg * 3 + c;
        const u32* p = g_wfrag + (size_t)((ct * 12) * 2) * 128 + lane * 4;
        *(uint4*)ah[0][c] = *(const uint4*)p;
        *(uint4*)al[0][c] = *(const uint4*)(p + 128);
    }
#pragma unroll
    for (int rt = 0; rt < 3; rt++) {
        int row = (rg * 3 + rt) * 8 + g;
        int o = row * 100 + tid2;
        bh[0][rt][0] = Ah32[o]; bh[0][rt][1] = Ah32[o + 4];
        bl[0][rt][0] = Al32[o]; bl[0][rt][1] = Al32[o + 4];
    }

#pragma unroll
    for (int k = 0; k < 12; k++) {
        const int cur = k & 1, nxt = cur ^ 1;
        if (k < 11) {
            const int kn = k + 1;
#pragma unroll
            for (int c = 0; c < 3; c++) {
                int ct = ct_base + cg * 3 + c;
                const u32* p = g_wfrag + (size_t)((ct * 12 + kn) * 2) * 128 + lane * 4;
                *(uint4*)ah[nxt][c] = *(const uint4*)p;
                *(uint4*)al[nxt][c] = *(const uint4*)(p + 128);
            }
#pragma unroll
            for (int rt = 0; rt < 3; rt++) {
                int row = (rg * 3 + rt) * 8 + g;
                int o = row * 100 + kn * 8 + tid2;
                bh[nxt][rt][0] = Ah32[o]; bh[nxt][rt][1] = Ah32[o + 4];
                bl[nxt][rt][0] = Al32[o]; bl[nxt][rt][1] = Al32[o + 4];
            }
        }
#pragma unroll
        for (int c = 0; c < 3; c++)
#pragma unroll
            for (int rt = 0; rt < 3; rt++) {
                mma16816(acc[c][rt], ah[cur][c], bh[cur][rt]);
                mma16816(acc[c][rt], al[cur][c], bh[cur][rt]);
                mma16816(acc[c][rt], ah[cur][c], bl[cur][rt]);
            }
    }
    if (MODE == 0) __syncthreads();   // all X reads done before Qimg overwrite

    if (MODE <= 1) {
        const u32 uh = (MODE == 0) ? U_QH : U_KH;
        const u32 ul = uh + 7200;
#pragma unroll
        for (int c = 0; c < 3; c++) {
            int ctl = cg * 3 + c;
#pragma unroll
            for (int rt = 0; rt < 3; rt++) {
                int rbase = (rg * 3 + rt) * 8;
#pragma unroll
                for (int q = 0; q < 4; q++) {
                    int feat = ctl * 16 + g + (q >> 1) * 8;
                    float v = (acc[c][rt][q] + __ldg(bias + feat)) * scale;
                    u32 hb, lb; bf_split(v, hb, lb);
                    u32 oh = __shfl_xor_sync(0xffffffffu, hb, 4);
                    u32 ol = __shfl_xor_sync(0xffffffffu, lb, 4);
                    if (!(g & 1)) {
                        int rr = rbase + tid2 * 2 + (q & 1);
                        int col = ctl * 8 + (g >> 1) + (q >> 1) * 4;
                        smu[uh + rr * 100 + col] = hb | (oh << 16);
                        smu[ul + rr * 100 + col] = lb | (ol << 16);
                    }
                }
            }
        }
    } else if (MODE == 2) {
#pragma unroll
        for (int c = 0; c < 3; c++) {
            int ctl = cg * 3 + c;
#pragma unroll
            for (int rt = 0; rt < 3; rt++) {
                int rbase = (rg * 3 + rt) * 8;
#pragma unroll
                for (int fp = 0; fp < 2; fp++) {
                    int F = ctl * 16 + g + fp * 8;
                    float b = __ldg(bias + F);
                    float v0 = acc[c][rt][fp * 2] + b;
                    float v1 = acc[c][rt][fp * 2 + 1] + b;
                    u32 lo; u32 hi = packbf(v0, v1, lo);
                    int tcol = (rbase >> 1) + tid2;
                    smu[U_VTH + F * 40 + tcol] = hi;
                    smu[U_VTL + F * 40 + tcol] = lo;
                }
            }
        }
    } else {
#pragma unroll
        for (int c = 0; c < 3; c++) {
            int ctl = cg * 3 + c;
#pragma unroll
            for (int rt = 0; rt < 3; rt++) {
                int rbase = (rg * 3 + rt) * 8;
#pragma unroll
                for (int q = 0; q < 4; q++) {
                    int feat = ctl * 16 + g + (q >> 1) * 8;
                    int rr = rbase + tid2 * 2 + (q & 1);
                    outg[rr * DIMX + feat] = acc[c][rt][q] + __ldg(bias + feat);
                }
            }
        }
    }
}

// ---------------- main kernel ----------------
__global__ __launch_bounds__(BLK, 1)
void earth_attn_kernel(
    const float* __restrict__ x,
    const float* __restrict__ mask,
    const float* __restrict__ bqkv,
    const float* __restrict__ bout,
    const float* __restrict__ tbl,
    float* __restrict__ out)
{
    extern __shared__ u32 smu[];
    const int c   = blockIdx.x;
    const int tid = threadIdx.x;
    const int wid = tid >> 5, lane = tid & 31;
    const int g = lane >> 2, tid2 = lane & 3;

    const int t_idx = c % TOWC;
    const int s_sh  = c / TOWC;
    const int m_idx = c % NWC;
    const float* maskg = mask + (size_t)m_idx * NSQ;
    const float* xsrc  = x + (size_t)c * (NTOK * DIMX);
    const float qscale = 0.1767766952966369f;
    u16* tb16 = (u16*)(smu + U_TB);
    const u16* gp = g_pidx + s_sh * NSQ;

    // ---- init: stage X into Qimg region, bias table slice ----
    for (int i = tid; i < NTOK * 48; i += BLK) {
        int r = i / 48, c4 = i - r * 48;
        float4 v = ((const float4*)xsrc)[i];
        int o = r * 100 + c4 * 2;
        u32 lo0, lo1;
        u32 hi0 = packbf(v.x, v.y, lo0);
        u32 hi1 = packbf(v.z, v.w, lo1);
        smu[U_QH + o] = hi0; smu[U_QH + o + 1] = hi1;
        smu[U_QL + o] = lo0; smu[U_QL + o + 1] = lo1;
    }
    for (int i = tid; i < TBLROWS * NH; i += BLK) {
        int r = i / NH, hh = i - r * NH;
        tb16[i] = __bfloat16_as_ushort(
            __float2bfloat16(__ldg(tbl + (r * TOWC + t_idx) * NH + hh)));
    }
    __syncthreads();

    // ---- projections (V, K first; Q last with deferred epi over X region)
    proj_pass<2>(tid, bqkv + 384, 1.0f,   smu, 24, nullptr);
    proj_pass<1>(tid, bqkv + 192, 1.0f,   smu, 12, nullptr);
    proj_pass<0>(tid, bqkv,       qscale, smu, 0,  nullptr);
    __syncthreads();

    // ---- attention: warp-independent (head, m-tile) tasks, no syncs ----
    for (int s4 = 0; s4 < 2; s4++) {
        int u = wid + s4 * 12;
        int h = u % 6;
        int stype = u / 6;
        int reps = (stype == 3) ? 2 : 1;
        for (int rep = 0; rep < reps; rep++) {
            int mt = (stype < 3) ? stype : (rep == 0 ? 4 : 3);
            int mb = (mt == 4) ? 56 : mt * 16;
            int r0 = mb + g, r1 = r0 + 8;

            // --- QK^T ---
            float acc[9][4];
#pragma unroll
            for (int nt = 0; nt < 9; nt++)
#pragma unroll
                for (int q = 0; q < 4; q++) acc[nt][q] = 0.0f;

            u32 ah[2][4], al[2][4];
#pragma unroll
            for (int ks = 0; ks < 2; ks++) {
                int ab = U_QH + r0 * 100 + h * 16 + ks * 8 + tid2;
                ah[ks][0] = smu[ab];        ah[ks][1] = smu[ab + 800];
                ah[ks][2] = smu[ab + 4];    ah[ks][3] = smu[ab + 804];
                al[ks][0] = smu[ab + 7200]; al[ks][1] = smu[ab + 8000];
                al[ks][2] = smu[ab + 7204]; al[ks][3] = smu[ab + 8004];
            }
#pragma unroll
            for (int nt = 0; nt < 9; nt++) {
#pragma unroll
                for (int ks = 0; ks < 2; ks++) {
                    int kb = U_KH + (nt * 8 + g) * 100 + h * 16 + ks * 8 + tid2;
                    u32 bh[2] = { smu[kb], smu[kb + 4] };
                    u32 bl[2] = { smu[kb + 7200], smu[kb + 7204] };
                    mma16816(acc[nt], ah[ks], bh);
                    mma16816(acc[nt], al[ks], bh);
                    mma16816(acc[nt], ah[ks], bl);
                }
            }

            // --- bias (pidx from L2, table from smem) + mask (from L2) ---
#pragma unroll
            for (int nt = 0; nt < 9; nt++) {
                int cc = nt * 8 + tid2 * 2;
                int e0 = r0 * 72 + cc, e1 = r1 * 72 + cc;
                float2 m0 = __ldg((const float2*)(maskg + e0));
                float2 m1 = __ldg((const float2*)(maskg + e1));
                acc[nt][0] += tbf(tb16[__ldg(gp + e0) + h])     + m0.x;
                acc[nt][1] += tbf(tb16[__ldg(gp + e0 + 1) + h]) + m0.y;
                acc[nt][2] += tbf(tb16[__ldg(gp + e1) + h])     + m1.x;
                acc[nt][3] += tbf(tb16[__ldg(gp + e1 + 1) + h]) + m1.y;
            }

            // --- softmax in registers ---
            float mx0 = -1e30f, mx1 = -1e30f;
#pragma unroll
            for (int nt = 0; nt < 9; nt++) {
                mx0 = fmaxf(mx0, fmaxf(acc[nt][0], acc[nt][1]));
                mx1 = fmaxf(mx1, fmaxf(acc[nt][2], acc[nt][3]));
            }
#pragma unroll
            for (int o = 1; o <= 2; o <<= 1) {
                mx0 = fmaxf(mx0, __shfl_xor_sync(0xffffffffu, mx0, o));
                mx1 = fmaxf(mx1, __shfl_xor_sync(0xffffffffu, mx1, o));
            }
            float s0 = 0.f, s1 = 0.f;
#pragma unroll
            for (int nt = 0; nt < 9; nt++) {
                acc[nt][0] = __expf(acc[nt][0] - mx0);
                acc[nt][1] = __expf(acc[nt][1] - mx0);
                acc[nt][2] = __expf(acc[nt][2] - mx1);
                acc[nt][3] = __expf(acc[nt][3] - mx1);
                s0 += acc[nt][0] + acc[nt][1];
                s1 += acc[nt][2] + acc[nt][3];
            }
#pragma unroll
            for (int o = 1; o <= 2; o <<= 1) {
                s0 += __shfl_xor_sync(0xffffffffu, s0, o);
                s1 += __shfl_xor_sync(0xffffffffu, s1, o);
            }
            float rv0 = 1.0f / s0, rv1 = 1.0f / s1;

            // --- pack P into A-fragments (register-to-register) ---
            u32 ph[4][4], pl[4][4], ph8[2], pl8[2];
#pragma unroll
            for (int j = 0; j < 4; j++) {
                ph[j][0] = packbf(acc[2*j][0] * rv0,   acc[2*j][1] * rv0,   pl[j][0]);
                ph[j][1] = packbf(acc[2*j][2] * rv1,   acc[2*j][3] * rv1,   pl[j][1]);
                ph[j][2] = packbf(acc[2*j+1][0] * rv0, acc[2*j+1][1] * rv0, pl[j][2]);
                ph[j][3] = packbf(acc[2*j+1][2] * rv1, acc[2*j+1][3] * rv1, pl[j][3]);
            }
            ph8[0] = packbf(acc[8][0] * rv0, acc[8][1] * rv0, pl8[0]);
            ph8[1] = packbf(acc[8][2] * rv1, acc[8][3] * rv1, pl8[1]);

            // --- AV: out = P @ v_h -> write Qimg head-h cols (own rows) ---
            bool w0 = (mt != 4);
#pragma unroll
            for (int nt2 = 0; nt2 < 4; nt2++) {
                float o2[4] = {0.f, 0.f, 0.f, 0.f};
                int vbase = U_VTH + (h * 32 + nt2 * 8 + g) * 40;
#pragma unroll
                for (int j = 0; j < 4; j++) {
                    u32 bh[2] = { smu[vbase + j * 8 + tid2], smu[vbase + j * 8 + 4 + tid2] };
                    u32 bl[2] = { smu[vbase + 7680 + j * 8 + tid2], smu[vbase + 7680 + j * 8 + 4 + tid2] };
                    mma16816(o2, ph[j], bh);
                    mma16816(o2, pl[j], bh);
                    mma16816(o2, ph[j], bl);
                }
                {
                    u32 b8h = smu[vbase + 32 + tid2];
                    u32 b8l = smu[vbase + 7680 + 32 + tid2];
                    mma16808(o2, ph8, b8h);
                    mma16808(o2, pl8, b8h);
                    mma16808(o2, ph8, b8l);
                }
                int col = h * 16 + nt2 * 4 + tid2;
                u32 lo; u32 hi = packbf(o2[0], o2[1], lo);
                if (w0) {
                    smu[U_QH + r0 * 100 + col] = hi;
                    smu[U_QL + r0 * 100 + col] = lo;
                }
                hi = packbf(o2[2], o2[3], lo);
                smu[U_QH + r1 * 100 + col] = hi;
                smu[U_QL + r1 * 100 + col] = lo;
            }
        }
    }
    __syncthreads();

    // ---- out projection (B = attn-out in Qimg) -> global ----
    proj_pass<3>(tid, bout, 1.0f, smu, 36, out + (size_t)c * (NTOK * DIMX));
}

extern "C" void kernel_launch(void* const* d_in, const int* in_sizes, int n_in,
                              void* d_out, int out_size)
{
    const float* x    = (const float*)d_in[0];
    const float* mask = (const float*)d_in[1];
    const float* wqkv = (const float*)d_in[2];
    const float* bqkv = (const float*)d_in[3];
    const float* wout = (const float*)d_in[4];
    const float* bout = (const float*)d_in[5];
    const float* tbl  = (const float*)d_in[6];
    float* out = (float*)d_out;

    int B_ = in_sizes[0] / (NTOK * DIMX);   // 1860

    build_wfrags<<<576, 256>>>(wqkv, wout);
    build_pidx<<<(NSH * NSQ + 255) / 256, 256>>>();

    cudaFuncSetAttribute(earth_attn_kernel,
                         cudaFuncAttributeMaxDynamicSharedMemorySize, SMEM_BYTES);
    earth_attn_kernel<<<B_, BLK, SMEM_BYTES>>>(x, mask, bqkv, bout, tbl, out);
}